// round 17
// baseline (speedup 1.0000x reference)
#include <cuda_runtime.h>
#include <cuda_fp16.h>
#include <cstdint>

#define BB 4
#define NN 4096
#define CC 64
#define TI 128             // i rows per block
#define TJ 128             // j (k-dim) per stage
#define NST (NN / TJ)      // 32 stages
#define NTHR 512           // 16 warps: wm = wid&7 (16 rows), kw = wid>>3 (64-wide k half)

// smem per stage: raw A fp32 tile + o half tile + sr
#define AROW 132                           // floats per A row (128 + 4 pad)
#define A_BYTES (TI * AROW * 4)            // 67584
#define OROWB 272                          // bytes per o row (128 + 8 halves); 272%128=16
#define O_BYTES (64 * OROWB)               // 17408
#define SR_BYTES 512
#define STG_B (A_BYTES + O_BYTES + SR_BYTES)   // 85504
#define SM_W2B  (2 * STG_B)                // 171008
#define SM_ZSHB (SM_W2B + 16384)           // 187392
#define SMEM_BYTES (SM_ZSHB + 1024)        // 188416

__device__ __half g_outT[BB * 64 * NN];    // [b][c][n] half
__device__ float  g_sl[BB * NN];
__device__ float  g_sr[BB * NN];

__device__ __forceinline__ float ex2f(float x) {
    float r;
    asm("ex2.approx.f32 %0, %1;" : "=f"(r) : "f"(x));
    return r;
}
__device__ __forceinline__ uint32_t smem_u32(const void* p) {
    uint32_t a;
    asm("{ .reg .u64 t; cvta.to.shared.u64 t, %1; cvt.u32.u64 %0, t; }" : "=r"(a) : "l"(p));
    return a;
}
__device__ __forceinline__ void mma_f16(float d[4], const uint32_t a[4],
                                        uint32_t b0, uint32_t b1) {
    asm volatile(
        "mma.sync.aligned.m16n8k16.row.col.f32.f16.f16.f32 "
        "{%0,%1,%2,%3},{%4,%5,%6,%7},{%8,%9},{%0,%1,%2,%3};"
        : "+f"(d[0]), "+f"(d[1]), "+f"(d[2]), "+f"(d[3])
        : "r"(a[0]), "r"(a[1]), "r"(a[2]), "r"(a[3]), "r"(b0), "r"(b1));
}
#define LDSM4(r, a) \
    asm volatile("ldmatrix.sync.aligned.m8n8.x4.shared.b16 {%0,%1,%2,%3}, [%4];" \
        : "=r"((r)[0]), "=r"((r)[1]), "=r"((r)[2]), "=r"((r)[3]) : "r"(a))
#define CP_ASYNC16(dst, src) \
    asm volatile("cp.async.cg.shared.global [%0], [%1], 16;" :: "r"(dst), "l"(src) : "memory")
#define CP_COMMIT() asm volatile("cp.async.commit_group;" ::: "memory")
#define CP_WAITALL() asm volatile("cp.async.wait_group 0;" ::: "memory")

// ---------------------------------------------------------------------------
// prep (proven): out = X@W1; g_outT half transposed (coalesced); sl, sr
// ---------------------------------------------------------------------------
#define HBUF_STRIDE 136
#define PREP_SMEM_FLOATS (4096 + 128 * 65 + 128 + (64 * HBUF_STRIDE) / 2 + 8)
__global__ __launch_bounds__(256) void prep_kernel(
    const float* __restrict__ X, const float* __restrict__ W1,
    const float* __restrict__ alpha)
{
    extern __shared__ float psm[];
    float*  W1s  = psm;
    float*  Xs   = psm + 4096;
    float*  al   = psm + 4096 + 128 * 65;
    float*  ar   = al + 64;
    __half* hbuf = reinterpret_cast<__half*>(ar + 64);

    const int tid = threadIdx.x;
    const int gr0 = blockIdx.x * 128;
    const int b0  = gr0 >> 12;
    const int n0  = gr0 & (NN - 1);

    for (int i = tid; i < 1024; i += 256)
        reinterpret_cast<float4*>(W1s)[i] = reinterpret_cast<const float4*>(W1)[i];
    for (int i = tid; i < 2048; i += 256) {
        int r = i >> 4, q = i & 15;
        float4 v = reinterpret_cast<const float4*>(X + (size_t)(gr0 + r) * CC)[q];
        Xs[r * 65 + 4 * q + 0] = v.x; Xs[r * 65 + 4 * q + 1] = v.y;
        Xs[r * 65 + 4 * q + 2] = v.z; Xs[r * 65 + 4 * q + 3] = v.w;
    }
    if (tid < 64)       al[tid]      = alpha[tid];
    else if (tid < 128) ar[tid - 64] = alpha[tid];
    __syncthreads();

    const int r  = tid >> 2;
    const int c0 = tid & 3;

    float acc0[16], acc1[16];
#pragma unroll
    for (int q = 0; q < 16; q++) { acc0[q] = 0.f; acc1[q] = 0.f; }
    const float4* W1v = reinterpret_cast<const float4*>(W1s);
#pragma unroll 4
    for (int k = 0; k < 64; k++) {
        float x0 = Xs[r * 65 + k];
        float x1 = Xs[(r + 64) * 65 + k];
#pragma unroll
        for (int h = 0; h < 4; h++) {
            float4 wv = W1v[k * 16 + 4 * c0 + h];
            acc0[4 * h + 0] += x0 * wv.x; acc1[4 * h + 0] += x1 * wv.x;
            acc0[4 * h + 1] += x0 * wv.y; acc1[4 * h + 1] += x1 * wv.y;
            acc0[4 * h + 2] += x0 * wv.z; acc1[4 * h + 2] += x1 * wv.z;
            acc0[4 * h + 3] += x0 * wv.w; acc1[4 * h + 3] += x1 * wv.w;
        }
    }

    float vl0 = 0.f, vr0 = 0.f, vl1 = 0.f, vr1 = 0.f;
#pragma unroll
    for (int q = 0; q < 16; q++) {
        float a_ = al[16 * c0 + q], r_ = ar[16 * c0 + q];
        vl0 += acc0[q] * a_; vr0 += acc0[q] * r_;
        vl1 += acc1[q] * a_; vr1 += acc1[q] * r_;
    }
#pragma unroll
    for (int o = 1; o <= 2; o <<= 1) {
        vl0 += __shfl_xor_sync(0xffffffffu, vl0, o);
        vr0 += __shfl_xor_sync(0xffffffffu, vr0, o);
        vl1 += __shfl_xor_sync(0xffffffffu, vl1, o);
        vr1 += __shfl_xor_sync(0xffffffffu, vr1, o);
    }
    if (c0 == 0) {
        g_sl[gr0 + r] = vl0;       g_sr[gr0 + r] = vr0;
        g_sl[gr0 + r + 64] = vl1;  g_sr[gr0 + r + 64] = vr1;
    }

#pragma unroll
    for (int q = 0; q < 16; q++) {
        int c = 16 * c0 + q;
        hbuf[c * HBUF_STRIDE + r]      = __float2half_rn(acc0[q]);
        hbuf[c * HBUF_STRIDE + r + 64] = __float2half_rn(acc1[q]);
    }
    __syncthreads();

    __half* oT = g_outT + (size_t)b0 * 64 * NN + n0;
#pragma unroll
    for (int p = 0; p < 4; p++) {
        int i = tid + 256 * p;
        int c = i >> 4, q = i & 15;
        uint4 v = *reinterpret_cast<const uint4*>(hbuf + c * HBUF_STRIDE + 8 * q);
        *reinterpret_cast<uint4*>(oT + (size_t)c * NN + 8 * q) = v;
    }
}

// ---------------------------------------------------------------------------
// stage compute, templated on diagonal handling; ks loop software-pipelined.
// ---------------------------------------------------------------------------
template<bool DIAG>
__device__ __forceinline__ void stage_compute(
    const float* __restrict__ As_r0, const float* __restrict__ As_r8,
    const float* __restrict__ srS, uint32_t wB,
    int kbase, int d0, float cl0, float cl1,
    float acc[8][4], float& zacc0, float& zacc1)
{
    float2 arl[2], arh[2], a8l[2], a8h[2], slo[2], shi[2];
#define LDFRAG(ks, sl_) do { \
        const int _kl = kbase + (ks) * 16; \
        arl[sl_] = *reinterpret_cast<const float2*>(As_r0 + _kl); \
        arh[sl_] = *reinterpret_cast<const float2*>(As_r0 + _kl + 8); \
        a8l[sl_] = *reinterpret_cast<const float2*>(As_r8 + _kl); \
        a8h[sl_] = *reinterpret_cast<const float2*>(As_r8 + _kl + 8); \
        slo[sl_] = *reinterpret_cast<const float2*>(srS + _kl); \
        shi[sl_] = *reinterpret_cast<const float2*>(srS + _kl + 8); \
    } while (0)

    LDFRAG(0, 0);
#pragma unroll
    for (int ks = 0; ks < 4; ks++) {
        const int cur = ks & 1;
        const uint32_t ko = (uint32_t)(ks * 32);
        uint32_t bb[16];
        LDSM4(bb + 0,  wB + ko);
        LDSM4(bb + 4,  wB + 16 * OROWB + ko);
        LDSM4(bb + 8,  wB + 32 * OROWB + ko);
        LDSM4(bb + 12, wB + 48 * OROWB + ko);
        if (ks < 3) LDFRAG(ks + 1, cur ^ 1);

        float2 _rl = arl[cur], _rh = arh[cur];
        float2 _8l = a8l[cur], _8h = a8h[cur];
        float2 _lo = slo[cur], _hi = shi[cur];

        if (DIAG) {
            const int kl = kbase + ks * 16;
            if (d0 == kl)          _rl.x = 1.f;
            else if (d0 == kl + 1) _rl.y = 1.f;
            else if (d0 == kl + 8) _rh.x = 1.f;
            else if (d0 == kl + 9) _rh.y = 1.f;
            const int d8 = d0 + 8;
            if (d8 == kl)          _8l.x = 1.f;
            else if (d8 == kl + 1) _8l.y = 1.f;
            else if (d8 == kl + 8) _8h.x = 1.f;
            else if (d8 == kl + 9) _8h.y = 1.f;
        }

        // w = ex2(max(t, 0.01 t)) * a,  t = (sl*log2e) * sr
        float t, u;
        t = cl0 * _lo.x; u = fmaxf(t, 0.01f * t); float f00 = ex2f(u) * _rl.x;
        t = cl0 * _lo.y; u = fmaxf(t, 0.01f * t); float f01 = ex2f(u) * _rl.y;
        t = cl0 * _hi.x; u = fmaxf(t, 0.01f * t); float f02 = ex2f(u) * _rh.x;
        t = cl0 * _hi.y; u = fmaxf(t, 0.01f * t); float f03 = ex2f(u) * _rh.y;
        t = cl1 * _lo.x; u = fmaxf(t, 0.01f * t); float f10 = ex2f(u) * _8l.x;
        t = cl1 * _lo.y; u = fmaxf(t, 0.01f * t); float f11 = ex2f(u) * _8l.y;
        t = cl1 * _hi.x; u = fmaxf(t, 0.01f * t); float f12 = ex2f(u) * _8h.x;
        t = cl1 * _hi.y; u = fmaxf(t, 0.01f * t); float f13 = ex2f(u) * _8h.y;

        zacc0 += (f00 + f01) + (f02 + f03);
        zacc1 += (f10 + f11) + (f12 + f13);

        uint32_t a[4];
        {
            __half2 h0 = __floats2half2_rn(f00, f01);
            __half2 h1 = __floats2half2_rn(f10, f11);
            __half2 h2 = __floats2half2_rn(f02, f03);
            __half2 h3 = __floats2half2_rn(f12, f13);
            a[0] = *reinterpret_cast<uint32_t*>(&h0);
            a[1] = *reinterpret_cast<uint32_t*>(&h1);
            a[2] = *reinterpret_cast<uint32_t*>(&h2);
            a[3] = *reinterpret_cast<uint32_t*>(&h3);
        }
#pragma unroll
        for (int g = 0; g < 4; g++) {
            mma_f16(acc[2 * g],     a, bb[4 * g],     bb[4 * g + 1]);
            mma_f16(acc[2 * g + 1], a, bb[4 * g + 2], bb[4 * g + 3]);
        }
    }
#undef LDFRAG
}

// ---------------------------------------------------------------------------
// attn (FUSED, TJ=128)
// ---------------------------------------------------------------------------
__global__ void __launch_bounds__(NTHR, 1) attn_kernel(
    const float* __restrict__ A_, const float* __restrict__ W2,
    float* __restrict__ out)
{
    extern __shared__ char sm[];
    const uint32_t smb = smem_u32(sm);
    float* W2s = reinterpret_cast<float*>(sm + SM_W2B);
    float* Zsh = reinterpret_cast<float*>(sm + SM_ZSHB);   // [2][128]

    const int b      = blockIdx.y;
    const int i_base = blockIdx.x * TI;
    const int tid    = threadIdx.x;
    const int lane   = tid & 31, wid = tid >> 5;
    const int wm = wid & 7, kw = wid >> 3;
    const int r = lane >> 2, cq = lane & 3;
    const int row0 = wm * 16 + r;             // rows row0, row0+8

    for (int i = tid; i < 1024; i += NTHR)
        reinterpret_cast<float4*>(W2s)[i] = reinterpret_cast<const float4*>(W2)[i];

    const __half* oTb = g_outT + (size_t)b * 64 * NN;
    const float*  srg = g_sr + b * NN;

    uint32_t adst[8]; int asrc[8];
#pragma unroll
    for (int p = 0; p < 8; p++) {
        int ch = tid + NTHR * p;
        int rr = ch >> 5, c = ch & 31;
        adst[p] = (uint32_t)(rr * (AROW * 4) + 16 * c);
        asrc[p] = (i_base + rr) * NN + 4 * c;
    }
    uint32_t odst[2]; int osrc[2];
#pragma unroll
    for (int p = 0; p < 2; p++) {
        int ch = tid + NTHR * p;
        int rr = ch >> 4, c = ch & 15;
        odst[p] = (uint32_t)(rr * OROWB + 16 * c);
        osrc[p] = rr * NN + 8 * c;
    }

    auto prefetch = [&](int s) {
        const int jb = s * TJ;
        const uint32_t bo = (uint32_t)(s & 1) * STG_B;
#pragma unroll
        for (int p = 0; p < 8; p++)
            CP_ASYNC16(smb + bo + adst[p], A_ + asrc[p] + jb);
#pragma unroll
        for (int p = 0; p < 2; p++)
            CP_ASYNC16(smb + bo + A_BYTES + odst[p], oTb + osrc[p] + jb);
        if (tid < 32)
            CP_ASYNC16(smb + bo + A_BYTES + O_BYTES + 16 * tid, srg + jb + 4 * tid);
        CP_COMMIT();
    };

    // per-row constants (signed; log2e folded in)
    const float cl0 = g_sl[b * NN + i_base + row0]     * 1.44269504f;
    const float cl1 = g_sl[b * NN + i_base + row0 + 8] * 1.44269504f;

    const uint32_t boff = (uint32_t)((((lane & 7) + ((lane >> 4) & 1) * 8)) * OROWB
                                     + ((lane >> 3) & 1) * 16);
    const int kbase = kw * 64 + 2 * cq;

    // per-buffer hoisted pointers
    const float* As_r0[2];
    const float* As_r8[2];
    const float* srS[2];
    uint32_t     wBp[2];
#pragma unroll
    for (int bf = 0; bf < 2; bf++) {
        const char* base = sm + (uint32_t)bf * STG_B;
        As_r0[bf] = reinterpret_cast<const float*>(base) + row0 * AROW;
        As_r8[bf] = reinterpret_cast<const float*>(base) + (row0 + 8) * AROW;
        srS[bf]   = reinterpret_cast<const float*>(base + A_BYTES + O_BYTES);
        wBp[bf]   = smb + (uint32_t)bf * STG_B + A_BYTES + boff + (uint32_t)(kw * 128);
    }

    float acc[8][4];
#pragma unroll
    for (int nt = 0; nt < 8; nt++)
#pragma unroll
        for (int e = 0; e < 4; e++) acc[nt][e] = 0.f;
    float zacc0 = 0.f, zacc1 = 0.f;

    const int dstage = i_base / TJ;

    prefetch(0);
    __syncthreads();   // covers W2s store ordering

    for (int s = 0; s < NST; s++) {
        CP_WAITALL();
        __syncthreads();
        if (s + 1 < NST) prefetch(s + 1);

        const int bf = s & 1;
        if (s == dstage)
            stage_compute<true>(As_r0[bf], As_r8[bf], srS[bf], wBp[bf],
                                kbase, row0, cl0, cl1, acc, zacc0, zacc1);
        else
            stage_compute<false>(As_r0[bf], As_r8[bf], srS[bf], wBp[bf],
                                 kbase, 0, cl0, cl1, acc, zacc0, zacc1);
    }

    // Z: reduce over cq lanes, per kw half
    zacc0 += __shfl_xor_sync(0xffffffffu, zacc0, 1);
    zacc0 += __shfl_xor_sync(0xffffffffu, zacc0, 2);
    zacc1 += __shfl_xor_sync(0xffffffffu, zacc1, 1);
    zacc1 += __shfl_xor_sync(0xffffffffu, zacc1, 2);
    if (cq == 0) {
        Zsh[kw * 128 + row0]     = zacc0;
        Zsh[kw * 128 + row0 + 8] = zacc1;
    }
    __syncthreads();

    float* aggS = reinterpret_cast<float*>(sm);   // 128 x 68, reuse buf0
    if (kw == 1) {
#pragma unroll
        for (int nt = 0; nt < 8; nt++) {
            int col = 8 * nt + 2 * cq;
            *reinterpret_cast<float2*>(aggS + row0 * 68 + col) =
                make_float2(acc[nt][0], acc[nt][1]);
            *reinterpret_cast<float2*>(aggS + (row0 + 8) * 68 + col) =
                make_float2(acc[nt][2], acc[nt][3]);
        }
    }
    __syncthreads();
    if (kw == 0) {
        float z0 = 1.0f / (Zsh[row0] + Zsh[128 + row0]);
        float z1 = 1.0f / (Zsh[row0 + 8] + Zsh[128 + row0 + 8]);
#pragma unroll
        for (int nt = 0; nt < 8; nt++) {
            int col = 8 * nt + 2 * cq;
            float2 p0 = *reinterpret_cast<const float2*>(aggS + row0 * 68 + col);
            float2 p1 = *reinterpret_cast<const float2*>(aggS + (row0 + 8) * 68 + col);
            *reinterpret_cast<float2*>(aggS + row0 * 68 + col) =
                make_float2((acc[nt][0] + p0.x) * z0, (acc[nt][1] + p0.y) * z0);
            *reinterpret_cast<float2*>(aggS + (row0 + 8) * 68 + col) =
                make_float2((acc[nt][2] + p1.x) * z1, (acc[nt][3] + p1.y) * z1);
        }
    }
    __syncthreads();

    // epilogue: out = aggS(128x64) @ W2(64x64)
    const int r0 = tid >> 2;
    const int c0 = tid & 3;
    float res[16];
#pragma unroll
    for (int q = 0; q < 16; q++) res[q] = 0.f;
#pragma unroll 8
    for (int k = 0; k < 64; k++) {
        float a0 = aggS[r0 * 68 + k];
#pragma unroll
        for (int q = 0; q < 16; q++)
            res[q] += a0 * W2s[k * 64 + c0 + 4 * q];
    }
    float* ob = out + (size_t)(b * NN + i_base + r0) * CC;
#pragma unroll
    for (int q = 0; q < 16; q++)
        ob[c0 + 4 * q] = res[q];
}

// ---------------------------------------------------------------------------
extern "C" void kernel_launch(void* const* d_in, const int* in_sizes, int n_in,
                              void* d_out, int out_size)
{
    (void)in_sizes; (void)n_in; (void)out_size;
    const float* X  = (const float*)d_in[0];
    const float* A_ = (const float*)d_in[1];
    const float* W1 = (const float*)d_in[2];
    const float* W2 = (const float*)d_in[3];
    const float* al = (const float*)d_in[4];
    float* out = (float*)d_out;

    cudaFuncSetAttribute(attn_kernel, cudaFuncAttributeMaxDynamicSharedMemorySize,
                         SMEM_BYTES);
    cudaFuncSetAttribute(prep_kernel, cudaFuncAttributeMaxDynamicSharedMemorySize,
                         PREP_SMEM_FLOATS * 4);

    prep_kernel<<<BB * NN / 128, 256, PREP_SMEM_FLOATS * 4>>>(X, W1, al);

    dim3 grid(NN / TI, BB);
    attn_kernel<<<grid, NTHR, SMEM_BYTES>>>(A_, W2, out);
}